// round 2
// baseline (speedup 1.0000x reference)
#include <cuda_runtime.h>
#include <cuda_bf16.h>
#include <cstdint>
#include <math.h>

#define NB 16384          // batch
#define NC 2              // contrast views
#define ND 1024           // feature dim
#define NSUB 16
#define NLAB 8
#define KG 128            // NSUB*NLAB groups
#define NROWS 32768       // NB*NC

// ---------------- scratch (device globals; no runtime allocation) ----------------
__device__ float g_centroid[KG * ND];      // 512 KB
__device__ float g_counts[KG];             // 2 * per-b count
__device__ int   g_gid[NB];
__device__ int   g_offsets[KG + 1];
__device__ int   g_cursor[KG];
__device__ int   g_rowlist[NB];
__device__ float g_cnorm[KG];              // ||centroid||^2
__device__ float g_S[(size_t)NROWS * KG];  // 16 MB  feat @ centroid^T
__device__ float g_rownorm[NROWS];         // ||feat_i||^2
__device__ float g_sqsum[KG];              // sum of sqrt(dist)
__device__ float g_invdens[KG];            // 1 / final density

// ---------------- K0a: gid, histogram, offsets, zero accumulators ----------------
__global__ void prep_kernel(const int* __restrict__ subject,
                            const int* __restrict__ labels,
                            float* __restrict__ out) {
    __shared__ int hist[KG];
    int t = threadIdx.x;  // 256
    if (t < KG) hist[t] = 0;
    __syncthreads();
    for (int b = t; b < NB; b += 256) {
        int g = subject[b] * NLAB + labels[b];
        g_gid[b] = g;
        atomicAdd(&hist[g], 1);
    }
    __syncthreads();
    if (t < KG) {
        g_counts[t] = 2.0f * (float)hist[t];
        g_sqsum[t] = 0.0f;
        g_cnorm[t] = 0.0f;
    }
    if (t == 0) {
        int acc = 0;
        for (int g = 0; g < KG; g++) {
            g_offsets[g] = acc;
            g_cursor[g] = acc;
            acc += hist[g];
        }
        g_offsets[KG] = acc;
        out[0] = 0.0f;
    }
}

// ---------------- K0b: scatter b indices into per-group lists ----------------
__global__ void scatter_kernel() {
    int b = blockIdx.x * blockDim.x + threadIdx.x;
    if (b < NB) {
        int g = g_gid[b];
        int pos = atomicAdd(&g_cursor[g], 1);
        g_rowlist[pos] = b;
    }
}

// ---------------- K1: centroids (block = (dchunk, group)) ----------------
__global__ __launch_bounds__(256) void centroid_kernel(const float* __restrict__ X) {
    int g = blockIdx.y;
    int d = blockIdx.x * 256 + threadIdx.x;     // 4 chunks of 256
    int beg = g_offsets[g], end = g_offsets[g + 1];
    float acc = 0.0f;
    int j = beg;
    for (; j + 4 <= end; j += 4) {
        int b0 = g_rowlist[j + 0];
        int b1 = g_rowlist[j + 1];
        int b2 = g_rowlist[j + 2];
        int b3 = g_rowlist[j + 3];
        const float* p0 = X + (size_t)b0 * (NC * ND) + d;
        const float* p1 = X + (size_t)b1 * (NC * ND) + d;
        const float* p2 = X + (size_t)b2 * (NC * ND) + d;
        const float* p3 = X + (size_t)b3 * (NC * ND) + d;
        acc += __ldg(p0) + __ldg(p0 + ND);
        acc += __ldg(p1) + __ldg(p1 + ND);
        acc += __ldg(p2) + __ldg(p2 + ND);
        acc += __ldg(p3) + __ldg(p3 + ND);
    }
    for (; j < end; j++) {
        int b = g_rowlist[j];
        const float* p = X + (size_t)b * (NC * ND) + d;
        acc += __ldg(p) + __ldg(p + ND);
    }
    float cnt = g_counts[g];
    float cv = (cnt > 0.0f) ? (acc / cnt) : 0.0f;
    g_centroid[g * ND + d] = cv;

    // block-reduce sum of cv^2 -> cnorm[g]
    float sq = cv * cv;
    #pragma unroll
    for (int off = 16; off; off >>= 1) sq += __shfl_down_sync(0xFFFFFFFFu, sq, off);
    __shared__ float wsum[8];
    if ((threadIdx.x & 31) == 0) wsum[threadIdx.x >> 5] = sq;
    __syncthreads();
    if (threadIdx.x == 0) {
        float s = 0.0f;
        #pragma unroll
        for (int w = 0; w < 8; w++) s += wsum[w];
        atomicAdd(&g_cnorm[g], s);
    }
}

// ---------------- K2: S = feat @ centroid^T  (+ rownorm) ----------------
// BM=128, BN=128(=KG), BK=8; 256 threads, 8x8 per-thread microtile.
__global__ __launch_bounds__(256) void gemm_kernel(const float* __restrict__ X) {
    __shared__ float As[8][128];
    __shared__ float Bs[8][128];
    const int t = threadIdx.x;
    const int ty = t >> 4;        // 0..15
    const int tx = t & 15;        // 0..15
    const int block_m = blockIdx.x * 128;
    const int c = block_m >> 14;          // / NB
    const int b0 = block_m & (NB - 1);
    const float* Abase = X + (size_t)b0 * (NC * ND) + (size_t)c * ND;

    const int lm = t >> 1;          // 0..127
    const int lk = (t & 1) * 4;     // 0 or 4

    float acc[8][8];
    #pragma unroll
    for (int i = 0; i < 8; i++)
        #pragma unroll
        for (int j = 0; j < 8; j++) acc[i][j] = 0.0f;
    float rn[8] = {0, 0, 0, 0, 0, 0, 0, 0};

    for (int k0 = 0; k0 < ND; k0 += 8) {
        float4 av = *(const float4*)(Abase + (size_t)lm * (NC * ND) + k0 + lk);
        float4 bv = *(const float4*)(&g_centroid[lm * ND + k0 + lk]);
        As[lk + 0][lm] = av.x; As[lk + 1][lm] = av.y;
        As[lk + 2][lm] = av.z; As[lk + 3][lm] = av.w;
        Bs[lk + 0][lm] = bv.x; Bs[lk + 1][lm] = bv.y;
        Bs[lk + 2][lm] = bv.z; Bs[lk + 3][lm] = bv.w;
        __syncthreads();
        #pragma unroll
        for (int k = 0; k < 8; k++) {
            float a[8], bb[8];
            *(float4*)&a[0] = *(float4*)&As[k][ty * 8];
            *(float4*)&a[4] = *(float4*)&As[k][ty * 8 + 4];
            *(float4*)&bb[0] = *(float4*)&Bs[k][tx * 8];
            *(float4*)&bb[4] = *(float4*)&Bs[k][tx * 8 + 4];
            if (tx == 0) {
                #pragma unroll
                for (int i = 0; i < 8; i++) rn[i] += a[i] * a[i];
            }
            #pragma unroll
            for (int i = 0; i < 8; i++)
                #pragma unroll
                for (int j = 0; j < 8; j++) acc[i][j] += a[i] * bb[j];
        }
        __syncthreads();
    }

    int row0 = block_m + ty * 8;
    #pragma unroll
    for (int i = 0; i < 8; i++) {
        float4* dst = (float4*)&g_S[(size_t)(row0 + i) * KG + tx * 8];
        dst[0] = make_float4(acc[i][0], acc[i][1], acc[i][2], acc[i][3]);
        dst[1] = make_float4(acc[i][4], acc[i][5], acc[i][6], acc[i][7]);
    }
    if (tx == 0) {
        #pragma unroll
        for (int i = 0; i < 8; i++) g_rownorm[row0 + i] = rn[i];
    }
}

// ---------------- K3: per-row dist -> per-group sum of sqrt(dist) ----------------
__global__ void dist_kernel() {
    __shared__ float bins[KG];
    int t = threadIdx.x;  // 256
    if (t < KG) bins[t] = 0.0f;
    __syncthreads();
    int i = blockIdx.x * 256 + t;  // grid 128 -> 32768 rows
    int b = i & (NB - 1);
    int g = g_gid[b];
    float s = g_S[(size_t)i * KG + g];
    float d2 = g_rownorm[i] - 2.0f * s + g_cnorm[g];
    float dist = sqrtf(fmaxf(d2, 0.0f));
    atomicAdd(&bins[g], sqrtf(dist));
    __syncthreads();
    if (t < KG) atomicAdd(&g_sqsum[t], bins[t]);
}

// ---------------- K4: density (128 values; sort + quantile clip + normalize) ----------------
__global__ void density_kernel() {
    int t = threadIdx.x;  // 128
    __shared__ float dens[KG];
    __shared__ float red[KG];
    __shared__ float sorted[KG];

    float cnt = g_counts[t];
    float d = (g_sqsum[t] / cnt) / logf(cnt + 10.0f);
    bool invalid = (cnt <= 1.0f);
    red[t] = invalid ? -3.4e38f : d;
    __syncthreads();
    for (int off = 64; off; off >>= 1) {
        if (t < off) red[t] = fmaxf(red[t], red[t + off]);
        __syncthreads();
    }
    float dmax = red[0];
    __syncthreads();
    if (invalid) d = dmax;
    dens[t] = d;
    __syncthreads();

    // rank sort (exact, stable via index tiebreak)
    int rank = 0;
    float v = d;
    for (int j = 0; j < KG; j++) {
        float w = dens[j];
        rank += (int)((w < v) || ((w == v) && (j < t)));
    }
    sorted[rank] = v;
    __syncthreads();

    // quantile(0.1): idx 12.7 ; quantile(0.9): idx 114.3 (linear interp)
    float qlo = sorted[12] + 0.7f * (sorted[13] - sorted[12]);
    float qhi = sorted[114] + 0.3f * (sorted[115] - sorted[114]);
    float dc = fminf(fmaxf(d, qlo), qhi);
    red[t] = dc;
    __syncthreads();
    for (int off = 64; off; off >>= 1) {
        if (t < off) red[t] += red[t + off];
        __syncthreads();
    }
    float mean = red[0] * (1.0f / 128.0f);
    float fin = 0.1f * dc / mean;   // DENS_TEMP = 0.1
    g_invdens[t] = 1.0f / fin;
}

// ---------------- K5: masked log-softmax loss (warp per row) ----------------
__global__ __launch_bounds__(256) void loss_kernel(const int* __restrict__ subject,
                                                   const int* __restrict__ labels,
                                                   float* __restrict__ out) {
    int warp_in_block = threadIdx.x >> 5;
    int lane = threadIdx.x & 31;
    int i = blockIdx.x * 8 + warp_in_block;   // row; grid 4096 * 8 warps = 32768
    int b = i & (NB - 1);

    float4 sv = *(const float4*)&g_S[(size_t)i * KG + lane * 4];
    float4 idv = *(const float4*)&g_invdens[lane * 4];
    float s0 = sv.x * idv.x;
    float s1 = sv.y * idv.y;
    float s2 = sv.z * idv.z;
    float s3 = sv.w * idv.w;

    float mx = fmaxf(fmaxf(s0, s1), fmaxf(s2, s3));
    #pragma unroll
    for (int off = 16; off; off >>= 1) mx = fmaxf(mx, __shfl_xor_sync(0xFFFFFFFFu, mx, off));

    int sub = subject[b];
    int lab = labels[b];

    float sim[4] = {s0, s1, s2, s3};
    float sumexp = 0.0f, possum = 0.0f;
    #pragma unroll
    for (int j = 0; j < 4; j++) {
        int g = lane * 4 + j;
        bool m = ((g & 7) == lab) && ((g >> 3) != sub);
        float p = m ? (sim[j] - mx) : 0.0f;   // pos = shifted_sim * mask (zeros kept!)
        sumexp += expf(p);                    // masked entries contribute exp(0)=1
        possum += p;                          // masked entries contribute 0
    }
    #pragma unroll
    for (int off = 16; off; off >>= 1) {
        sumexp += __shfl_xor_sync(0xFFFFFFFFu, sumexp, off);
        possum += __shfl_xor_sync(0xFFFFFFFFu, possum, off);
    }

    __shared__ float wloss[8];
    if (lane == 0) {
        // row_loss = LSE - (sum of positives)/15 ; mask.sum() == 15 exactly
        wloss[warp_in_block] = logf(sumexp) - possum * (1.0f / 15.0f);
    }
    __syncthreads();
    if (threadIdx.x == 0) {
        float s = 0.0f;
        #pragma unroll
        for (int w = 0; w < 8; w++) s += wloss[w];
        atomicAdd(out, s * (1.0f / (float)NROWS));
    }
}

// ---------------- launch ----------------
extern "C" void kernel_launch(void* const* d_in, const int* in_sizes, int n_in,
                              void* d_out, int out_size) {
    const float* X       = (const float*)d_in[0];
    const int*   subject = (const int*)d_in[1];
    const int*   labels  = (const int*)d_in[2];
    float* out = (float*)d_out;

    prep_kernel<<<1, 256>>>(subject, labels, out);
    scatter_kernel<<<64, 256>>>();
    dim3 cgrid(ND / 256, KG);
    centroid_kernel<<<cgrid, 256>>>(X);
    gemm_kernel<<<NROWS / 128, 256>>>(X);
    dist_kernel<<<NROWS / 256, 256>>>();
    density_kernel<<<1, 128>>>();
    loss_kernel<<<NROWS / 8, 256>>>(subject, labels, out);
}

// round 4
// speedup vs baseline: 2.1107x; 2.1107x over previous
#include <cuda_runtime.h>
#include <cuda_bf16.h>
#include <cstdint>
#include <math.h>

#define NB 16384          // batch
#define NC 2              // contrast views
#define ND 1024           // feature dim
#define NSUB 16
#define NLAB 8
#define KG 128            // NSUB*NLAB groups
#define NROWS 32768       // NB*NC
#define BK 32             // k-chunk (elements)
#define NCHUNK (ND / BK)  // 32
#define LDS_STRIDE 40     // bf16 elems per smem row (80B = 20 banks, conflict-free)

// ---------------- scratch (device globals; no runtime allocation) ----------------
__device__ __align__(16) __nv_bfloat16 g_cent_h[KG * ND];   // centroid hi bf16
__device__ __align__(16) __nv_bfloat16 g_cent_l[KG * ND];   // centroid lo bf16
__device__ float g_counts[KG];
__device__ int   g_gid[NB];
__device__ int   g_offsets[KG + 1];
__device__ int   g_cursor[KG];
__device__ int   g_rowlist[NB];
__device__ float g_cnorm[KG];
__device__ float g_S[(size_t)NROWS * KG];  // 16 MB
__device__ float g_rownorm[NROWS];
__device__ float g_sqsum[KG];
__device__ float g_invdens[KG];

// ---------------- helpers ----------------
// pack two fp32 into bf16x2: low half = lo, high half = hi
__device__ __forceinline__ uint32_t pack_bf16(float lo, float hi) {
    uint32_t r;
    asm("cvt.rn.bf16x2.f32 %0, %1, %2;" : "=r"(r) : "f"(hi), "f"(lo));
    return r;
}
__device__ __forceinline__ float bf_lo(uint32_t v) {
    return __bfloat162float(__ushort_as_bfloat16((unsigned short)(v & 0xFFFFu)));
}
__device__ __forceinline__ float bf_hi(uint32_t v) {
    return __bfloat162float(__ushort_as_bfloat16((unsigned short)(v >> 16)));
}
__device__ __forceinline__ void hmma_bf16(float* d, const uint32_t* a, const uint32_t* b) {
    asm volatile(
        "mma.sync.aligned.m16n8k16.row.col.f32.bf16.bf16.f32 "
        "{%0,%1,%2,%3}, {%4,%5,%6,%7}, {%8,%9}, {%0,%1,%2,%3};"
        : "+f"(d[0]), "+f"(d[1]), "+f"(d[2]), "+f"(d[3])
        : "r"(a[0]), "r"(a[1]), "r"(a[2]), "r"(a[3]), "r"(b[0]), "r"(b[1]));
}

// ---------------- K0a: gid, histogram, offsets, zero accumulators ----------------
__global__ void prep_kernel(const int* __restrict__ subject,
                            const int* __restrict__ labels,
                            float* __restrict__ out) {
    __shared__ int hist[KG];
    int t = threadIdx.x;  // 256
    if (t < KG) hist[t] = 0;
    __syncthreads();
    for (int b = t; b < NB; b += 256) {
        int g = subject[b] * NLAB + labels[b];
        g_gid[b] = g;
        atomicAdd(&hist[g], 1);
    }
    __syncthreads();
    if (t < KG) {
        g_counts[t] = 2.0f * (float)hist[t];
        g_sqsum[t] = 0.0f;
        g_cnorm[t] = 0.0f;
    }
    if (t == 0) {
        int acc = 0;
        for (int g = 0; g < KG; g++) {
            g_offsets[g] = acc;
            g_cursor[g] = acc;
            acc += hist[g];
        }
        g_offsets[KG] = acc;
        out[0] = 0.0f;
    }
}

// ---------------- K0b: scatter ----------------
__global__ void scatter_kernel() {
    int b = blockIdx.x * blockDim.x + threadIdx.x;
    if (b < NB) {
        int g = g_gid[b];
        int pos = atomicAdd(&g_cursor[g], 1);
        g_rowlist[pos] = b;
    }
}

// ---------------- K1: centroids (fp32) -> bf16 hi/lo + cnorm ----------------
__global__ __launch_bounds__(256) void centroid_kernel(const float* __restrict__ X) {
    int g = blockIdx.y;
    int d = blockIdx.x * 256 + threadIdx.x;
    int beg = g_offsets[g], end = g_offsets[g + 1];
    float acc = 0.0f;
    int j = beg;
    for (; j + 4 <= end; j += 4) {
        int b0 = g_rowlist[j + 0], b1 = g_rowlist[j + 1];
        int b2 = g_rowlist[j + 2], b3 = g_rowlist[j + 3];
        const float* p0 = X + (size_t)b0 * (NC * ND) + d;
        const float* p1 = X + (size_t)b1 * (NC * ND) + d;
        const float* p2 = X + (size_t)b2 * (NC * ND) + d;
        const float* p3 = X + (size_t)b3 * (NC * ND) + d;
        acc += __ldg(p0) + __ldg(p0 + ND);
        acc += __ldg(p1) + __ldg(p1 + ND);
        acc += __ldg(p2) + __ldg(p2 + ND);
        acc += __ldg(p3) + __ldg(p3 + ND);
    }
    for (; j < end; j++) {
        int b = g_rowlist[j];
        const float* p = X + (size_t)b * (NC * ND) + d;
        acc += __ldg(p) + __ldg(p + ND);
    }
    float cnt = g_counts[g];
    float cv = (cnt > 0.0f) ? (acc / cnt) : 0.0f;

    // split fp32 -> bf16 hi + lo residual
    __nv_bfloat16 ch = __float2bfloat16(cv);
    float chf = __bfloat162float(ch);
    __nv_bfloat16 cl = __float2bfloat16(cv - chf);
    g_cent_h[g * ND + d] = ch;
    g_cent_l[g * ND + d] = cl;

    float sq = cv * cv;
    #pragma unroll
    for (int off = 16; off; off >>= 1) sq += __shfl_down_sync(0xFFFFFFFFu, sq, off);
    __shared__ float wsum[8];
    if ((threadIdx.x & 31) == 0) wsum[threadIdx.x >> 5] = sq;
    __syncthreads();
    if (threadIdx.x == 0) {
        float s = 0.0f;
        #pragma unroll
        for (int w = 0; w < 8; w++) s += wsum[w];
        atomicAdd(&g_cnorm[g], s);
    }
}

// ---------------- K2: split-bf16 HMMA GEMM: S = feat @ centroid^T (+ rownorm) ----------------
// CTA 128x128, 8 warps (4x2), warp tile 32x64, BK=32, register prefetch of next chunk.
__global__ __launch_bounds__(256, 1) void gemm_kernel(const float* __restrict__ X) {
    __shared__ __nv_bfloat16 sAh[128][LDS_STRIDE];
    __shared__ __nv_bfloat16 sAl[128][LDS_STRIDE];
    __shared__ __nv_bfloat16 sBh[128][LDS_STRIDE];
    __shared__ __nv_bfloat16 sBl[128][LDS_STRIDE];

    const int t = threadIdx.x;
    const int wid = t >> 5;
    const int lane = t & 31;
    const int lr = lane >> 2;        // 0..7
    const int lc = (lane & 3) * 2;   // 0,2,4,6
    const int warp_m = (wid & 3) * 32;
    const int warp_n = (wid >> 2) * 64;

    const int block_m = blockIdx.x * 128;
    const int c = block_m >> 14;           // view index (block_m / NB)
    const int b0 = block_m & (NB - 1);
    const float* Abase = X + (size_t)b0 * (NC * ND) + (size_t)c * ND;

    // A load mapping: 4 passes; row = p*32 + (t>>3), k = (t&7)*4
    const int ar = t >> 3;       // 0..31
    const int ak = (t & 7) * 4;  // 0..28
    // B load mapping: 2 passes; row = p*64 + (t>>2), k = (t&3)*8
    const int br = t >> 2;       // 0..63
    const int bk = (t & 3) * 8;  // 0,8,16,24

    float acc[2][8][4];
    #pragma unroll
    for (int mi = 0; mi < 2; mi++)
        #pragma unroll
        for (int ni = 0; ni < 8; ni++)
            #pragma unroll
            for (int j = 0; j < 4; j++) acc[mi][ni][j] = 0.0f;
    float rn[4] = {0, 0, 0, 0};

    // prefetch chunk 0
    float4 pav[4];
    uint4 pbh[2], pbl[2];
    #pragma unroll
    for (int p = 0; p < 4; p++)
        pav[p] = *(const float4*)(Abase + (size_t)(p * 32 + ar) * (NC * ND) + ak);
    #pragma unroll
    for (int p = 0; p < 2; p++) {
        pbh[p] = *(const uint4*)&g_cent_h[(p * 64 + br) * ND + bk];
        pbl[p] = *(const uint4*)&g_cent_l[(p * 64 + br) * ND + bk];
    }

    for (int chk = 0; chk < NCHUNK; chk++) {
        // ---- convert & store prefetched chunk to smem ----
        #pragma unroll
        for (int p = 0; p < 4; p++) {
            float4 v = pav[p];
            rn[p] += v.x * v.x + v.y * v.y + v.z * v.z + v.w * v.w;
            uint32_t h0 = pack_bf16(v.x, v.y);
            uint32_t h1 = pack_bf16(v.z, v.w);
            uint32_t l0 = pack_bf16(v.x - bf_lo(h0), v.y - bf_hi(h0));
            uint32_t l1 = pack_bf16(v.z - bf_lo(h1), v.w - bf_hi(h1));
            int r = p * 32 + ar;
            *(uint2*)&sAh[r][ak] = make_uint2(h0, h1);
            *(uint2*)&sAl[r][ak] = make_uint2(l0, l1);
        }
        #pragma unroll
        for (int p = 0; p < 2; p++) {
            int g = p * 64 + br;
            *(uint4*)&sBh[g][bk] = pbh[p];
            *(uint4*)&sBl[g][bk] = pbl[p];
        }
        __syncthreads();

        // ---- issue global prefetch for next chunk (overlaps with MMA below) ----
        if (chk + 1 < NCHUNK) {
            const int k0 = (chk + 1) * BK;
            #pragma unroll
            for (int p = 0; p < 4; p++)
                pav[p] = *(const float4*)(Abase + (size_t)(p * 32 + ar) * (NC * ND) + k0 + ak);
            #pragma unroll
            for (int p = 0; p < 2; p++) {
                pbh[p] = *(const uint4*)&g_cent_h[(p * 64 + br) * ND + k0 + bk];
                pbl[p] = *(const uint4*)&g_cent_l[(p * 64 + br) * ND + k0 + bk];
            }
        }

        // ---- MMA over the chunk (2 k16 sub-steps) ----
        #pragma unroll
        for (int kk = 0; kk < BK; kk += 16) {
            uint32_t ah[2][4], al[2][4];
            #pragma unroll
            for (int mi = 0; mi < 2; mi++) {
                int m = warp_m + mi * 16;
                ah[mi][0] = *(const uint32_t*)&sAh[m + lr][kk + lc];
                ah[mi][1] = *(const uint32_t*)&sAh[m + lr + 8][kk + lc];
                ah[mi][2] = *(const uint32_t*)&sAh[m + lr][kk + lc + 8];
                ah[mi][3] = *(const uint32_t*)&sAh[m + lr + 8][kk + lc + 8];
                al[mi][0] = *(const uint32_t*)&sAl[m + lr][kk + lc];
                al[mi][1] = *(const uint32_t*)&sAl[m + lr + 8][kk + lc];
                al[mi][2] = *(const uint32_t*)&sAl[m + lr][kk + lc + 8];
                al[mi][3] = *(const uint32_t*)&sAl[m + lr + 8][kk + lc + 8];
            }
            uint32_t bh[8][2], bl[8][2];
            #pragma unroll
            for (int ni = 0; ni < 8; ni++) {
                int g = warp_n + ni * 8 + lr;
                bh[ni][0] = *(const uint32_t*)&sBh[g][kk + lc];
                bh[ni][1] = *(const uint32_t*)&sBh[g][kk + lc + 8];
                bl[ni][0] = *(const uint32_t*)&sBl[g][kk + lc];
                bl[ni][1] = *(const uint32_t*)&sBl[g][kk + lc + 8];
            }
            #pragma unroll
            for (int mi = 0; mi < 2; mi++)
                #pragma unroll
                for (int ni = 0; ni < 8; ni++) {
                    hmma_bf16(acc[mi][ni], ah[mi], bh[ni]);
                    hmma_bf16(acc[mi][ni], ah[mi], bl[ni]);
                    hmma_bf16(acc[mi][ni], al[mi], bh[ni]);
                }
        }
        __syncthreads();
    }

    // ---- rownorm: reduce over the 8 lanes sharing each row ----
    #pragma unroll
    for (int p = 0; p < 4; p++) {
        float v = rn[p];
        v += __shfl_xor_sync(0xFFFFFFFFu, v, 1);
        v += __shfl_xor_sync(0xFFFFFFFFu, v, 2);
        v += __shfl_xor_sync(0xFFFFFFFFu, v, 4);
        if ((t & 7) == 0) g_rownorm[block_m + p * 32 + ar] = v;
    }

    // ---- epilogue: write S ----
    #pragma unroll
    for (int mi = 0; mi < 2; mi++) {
        #pragma unroll
        for (int ni = 0; ni < 8; ni++) {
            int row = block_m + warp_m + mi * 16 + lr;
            int col = warp_n + ni * 8 + lc;
            *(float2*)&g_S[(size_t)row * KG + col] =
                make_float2(acc[mi][ni][0], acc[mi][ni][1]);
            *(float2*)&g_S[(size_t)(row + 8) * KG + col] =
                make_float2(acc[mi][ni][2], acc[mi][ni][3]);
        }
    }
}

// ---------------- K3: per-row dist -> per-group sum of sqrt(dist) ----------------
__global__ void dist_kernel() {
    __shared__ float bins[KG];
    int t = threadIdx.x;
    if (t < KG) bins[t] = 0.0f;
    __syncthreads();
    int i = blockIdx.x * 256 + t;
    int b = i & (NB - 1);
    int g = g_gid[b];
    float s = g_S[(size_t)i * KG + g];
    float d2 = g_rownorm[i] - 2.0f * s + g_cnorm[g];
    float dist = sqrtf(fmaxf(d2, 0.0f));
    atomicAdd(&bins[g], sqrtf(dist));
    __syncthreads();
    if (t < KG) atomicAdd(&g_sqsum[t], bins[t]);
}

// ---------------- K4: density ----------------
__global__ void density_kernel() {
    int t = threadIdx.x;  // 128
    __shared__ float dens[KG];
    __shared__ float red[KG];
    __shared__ float sorted[KG];

    float cnt = g_counts[t];
    float d = (g_sqsum[t] / cnt) / logf(cnt + 10.0f);
    bool invalid = (cnt <= 1.0f);
    red[t] = invalid ? -3.4e38f : d;
    __syncthreads();
    for (int off = 64; off; off >>= 1) {
        if (t < off) red[t] = fmaxf(red[t], red[t + off]);
        __syncthreads();
    }
    float dmax = red[0];
    __syncthreads();
    if (invalid) d = dmax;
    dens[t] = d;
    __syncthreads();

    int rank = 0;
    float v = d;
    for (int j = 0; j < KG; j++) {
        float w = dens[j];
        rank += (int)((w < v) || ((w == v) && (j < t)));
    }
    sorted[rank] = v;
    __syncthreads();

    float qlo = sorted[12] + 0.7f * (sorted[13] - sorted[12]);
    float qhi = sorted[114] + 0.3f * (sorted[115] - sorted[114]);
    float dc = fminf(fmaxf(d, qlo), qhi);
    red[t] = dc;
    __syncthreads();
    for (int off = 64; off; off >>= 1) {
        if (t < off) red[t] += red[t + off];
        __syncthreads();
    }
    float mean = red[0] * (1.0f / 128.0f);
    float fin = 0.1f * dc / mean;
    g_invdens[t] = 1.0f / fin;
}

// ---------------- K5: masked log-softmax loss ----------------
__global__ __launch_bounds__(256) void loss_kernel(const int* __restrict__ subject,
                                                   const int* __restrict__ labels,
                                                   float* __restrict__ out) {
    int warp_in_block = threadIdx.x >> 5;
    int lane = threadIdx.x & 31;
    int i = blockIdx.x * 8 + warp_in_block;
    int b = i & (NB - 1);

    float4 sv = *(const float4*)&g_S[(size_t)i * KG + lane * 4];
    float4 idv = *(const float4*)&g_invdens[lane * 4];
    float s0 = sv.x * idv.x, s1 = sv.y * idv.y, s2 = sv.z * idv.z, s3 = sv.w * idv.w;

    float mx = fmaxf(fmaxf(s0, s1), fmaxf(s2, s3));
    #pragma unroll
    for (int off = 16; off; off >>= 1) mx = fmaxf(mx, __shfl_xor_sync(0xFFFFFFFFu, mx, off));

    int sub = subject[b];
    int lab = labels[b];

    float sim[4] = {s0, s1, s2, s3};
    float sumexp = 0.0f, possum = 0.0f;
    #pragma unroll
    for (int j = 0; j < 4; j++) {
        int g = lane * 4 + j;
        bool m = ((g & 7) == lab) && ((g >> 3) != sub);
        float p = m ? (sim[j] - mx) : 0.0f;
        sumexp += expf(p);
        possum += p;
    }
    #pragma unroll
    for (int off = 16; off; off >>= 1) {
        sumexp += __shfl_xor_sync(0xFFFFFFFFu, sumexp, off);
        possum += __shfl_xor_sync(0xFFFFFFFFu, possum, off);
    }

    __shared__ float wloss[8];
    if (lane == 0)
        wloss[warp_in_block] = logf(sumexp) - possum * (1.0f / 15.0f);
    __syncthreads();
    if (threadIdx.x == 0) {
        float s = 0.0f;
        #pragma unroll
        for (int w = 0; w < 8; w++) s += wloss[w];
        atomicAdd(out, s * (1.0f / (float)NROWS));
    }
}

// ---------------- launch ----------------
extern "C" void kernel_launch(void* const* d_in, const int* in_sizes, int n_in,
                              void* d_out, int out_size) {
    const float* X       = (const float*)d_in[0];
    const int*   subject = (const int*)d_in[1];
    const int*   labels  = (const int*)d_in[2];
    float* out = (float*)d_out;

    prep_kernel<<<1, 256>>>(subject, labels, out);
    scatter_kernel<<<64, 256>>>();
    dim3 cgrid(ND / 256, KG);
    centroid_kernel<<<cgrid, 256>>>(X);
    gemm_kernel<<<NROWS / 128, 256>>>(X);
    dist_kernel<<<NROWS / 256, 256>>>();
    density_kernel<<<1, 128>>>();
    loss_kernel<<<NROWS / 8, 256>>>(subject, labels, out);
}

// round 6
// speedup vs baseline: 2.1198x; 1.0043x over previous
#include <cuda_runtime.h>
#include <cuda_bf16.h>
#include <cstdint>
#include <math.h>

#define NB 16384          // batch
#define NC 2              // contrast views
#define ND 1024           // feature dim
#define NSUB 16
#define NLAB 8
#define KG 128            // NSUB*NLAB groups
#define NROWS 32768       // NB*NC
#define BK 32             // k-chunk (elements)
#define NCHUNK (ND / BK)  // 32
#define LDSS 40           // bf16 elems per smem row (80B = 20 banks, conflict-free)

// smem element offsets (bf16 units) inside dynamic smem
#define OFF_AH 0                     // [2][64][LDSS]
#define OFF_AL (2 * 64 * LDSS)       // 5120
#define OFF_BH (2 * OFF_AL)          // 10240  [2][128][LDSS]
#define OFF_BL (OFF_BH + 2 * 128 * LDSS)  // 20480
#define DYN_SMEM ((OFF_BL + 2 * 128 * LDSS) * 2)  // 30720 elems = 61440 bytes

// ---------------- scratch (device globals; no runtime allocation) ----------------
__device__ __align__(16) __nv_bfloat16 g_cent_h[KG * ND];
__device__ __align__(16) __nv_bfloat16 g_cent_l[KG * ND];
__device__ float g_counts[KG];
__device__ int   g_hist[KG];
__device__ int   g_gid[NB];
__device__ int   g_offsets[KG + 1];
__device__ int   g_cursor[KG];
__device__ int   g_rowlist[NB];
__device__ float g_cnorm[KG];
__device__ float g_S[(size_t)NROWS * KG];  // 16 MB
__device__ float g_rownorm[NROWS];
__device__ float g_sqsum[KG];
__device__ float g_invdens[KG];

// ---------------- helpers ----------------
__device__ __forceinline__ uint32_t pack_bf16(float lo, float hi) {
    uint32_t r;
    asm("cvt.rn.bf16x2.f32 %0, %1, %2;" : "=r"(r) : "f"(hi), "f"(lo));
    return r;
}
__device__ __forceinline__ float bf_lo(uint32_t v) {
    return __bfloat162float(__ushort_as_bfloat16((unsigned short)(v & 0xFFFFu)));
}
__device__ __forceinline__ float bf_hi(uint32_t v) {
    return __bfloat162float(__ushort_as_bfloat16((unsigned short)(v >> 16)));
}
__device__ __forceinline__ void hmma_bf16(float* d, const uint32_t* a, const uint32_t* b) {
    asm volatile(
        "mma.sync.aligned.m16n8k16.row.col.f32.bf16.bf16.f32 "
        "{%0,%1,%2,%3}, {%4,%5,%6,%7}, {%8,%9}, {%0,%1,%2,%3};"
        : "+f"(d[0]), "+f"(d[1]), "+f"(d[2]), "+f"(d[3])
        : "r"(a[0]), "r"(a[1]), "r"(a[2]), "r"(a[3]), "r"(b[0]), "r"(b[1]));
}

// ---------------- K0a: zero accumulators ----------------
__global__ void zero_kernel(float* __restrict__ out) {
    int t = threadIdx.x;  // 128
    g_hist[t] = 0;
    g_sqsum[t] = 0.0f;
    g_cnorm[t] = 0.0f;
    if (t == 0) out[0] = 0.0f;
}

// ---------------- K0b: gid + histogram (64 blocks) ----------------
__global__ void hist_kernel(const int* __restrict__ subject,
                            const int* __restrict__ labels) {
    __shared__ int hist[KG];
    int t = threadIdx.x;
    if (t < KG) hist[t] = 0;
    __syncthreads();
    int b = blockIdx.x * 256 + t;
    int g = subject[b] * NLAB + labels[b];
    g_gid[b] = g;
    atomicAdd(&hist[g], 1);
    __syncthreads();
    if (t < KG && hist[t]) atomicAdd(&g_hist[t], hist[t]);
}

// ---------------- K0c: offsets / counts ----------------
__global__ void offsets_kernel() {
    int t = threadIdx.x;  // 128
    __shared__ int h[KG];
    h[t] = g_hist[t];
    __syncthreads();
    int acc = 0;
    for (int j = 0; j < t; j++) acc += h[j];
    g_offsets[t] = acc;
    g_cursor[t] = acc;
    g_counts[t] = 2.0f * (float)h[t];
    if (t == KG - 1) g_offsets[KG] = acc + h[t];
}

// ---------------- K0d: scatter ----------------
__global__ void scatter_kernel() {
    int b = blockIdx.x * blockDim.x + threadIdx.x;
    if (b < NB) {
        int g = g_gid[b];
        int pos = atomicAdd(&g_cursor[g], 1);
        g_rowlist[pos] = b;
    }
}

// ---------------- K1: centroids (fp32) -> bf16 hi/lo + cnorm ----------------
__global__ __launch_bounds__(256) void centroid_kernel(const float* __restrict__ X) {
    int g = blockIdx.y;
    int d = blockIdx.x * 256 + threadIdx.x;
    int beg = g_offsets[g], end = g_offsets[g + 1];
    float acc = 0.0f;
    int j = beg;
    for (; j + 4 <= end; j += 4) {
        int b0 = g_rowlist[j + 0], b1 = g_rowlist[j + 1];
        int b2 = g_rowlist[j + 2], b3 = g_rowlist[j + 3];
        const float* p0 = X + (size_t)b0 * (NC * ND) + d;
        const float* p1 = X + (size_t)b1 * (NC * ND) + d;
        const float* p2 = X + (size_t)b2 * (NC * ND) + d;
        const float* p3 = X + (size_t)b3 * (NC * ND) + d;
        acc += __ldg(p0) + __ldg(p0 + ND);
        acc += __ldg(p1) + __ldg(p1 + ND);
        acc += __ldg(p2) + __ldg(p2 + ND);
        acc += __ldg(p3) + __ldg(p3 + ND);
    }
    for (; j < end; j++) {
        int b = g_rowlist[j];
        const float* p = X + (size_t)b * (NC * ND) + d;
        acc += __ldg(p) + __ldg(p + ND);
    }
    float cnt = g_counts[g];
    float cv = (cnt > 0.0f) ? (acc / cnt) : 0.0f;

    __nv_bfloat16 ch = __float2bfloat16(cv);
    float chf = __bfloat162float(ch);
    __nv_bfloat16 cl = __float2bfloat16(cv - chf);
    g_cent_h[g * ND + d] = ch;
    g_cent_l[g * ND + d] = cl;

    float sq = cv * cv;
    #pragma unroll
    for (int off = 16; off; off >>= 1) sq += __shfl_down_sync(0xFFFFFFFFu, sq, off);
    __shared__ float wsum[8];
    if ((threadIdx.x & 31) == 0) wsum[threadIdx.x >> 5] = sq;
    __syncthreads();
    if (threadIdx.x == 0) {
        float s = 0.0f;
        #pragma unroll
        for (int w = 0; w < 8; w++) s += wsum[w];
        atomicAdd(&g_cnorm[g], s);
    }
}

// ---------------- K2: split-bf16 HMMA GEMM, double-buffered ----------------
// CTA 64x128, 4 warps (2x2), warp tile 32x64, BK=32, 2-stage smem pipeline.
__global__ __launch_bounds__(128, 2) void gemm_kernel(const float* __restrict__ X) {
    extern __shared__ __nv_bfloat16 sm[];
    __nv_bfloat16* sAh = sm + OFF_AH;
    __nv_bfloat16* sAl = sm + OFF_AL;
    __nv_bfloat16* sBh = sm + OFF_BH;
    __nv_bfloat16* sBl = sm + OFF_BL;

    const int t = threadIdx.x;
    const int wid = t >> 5;
    const int lane = t & 31;
    const int lr = lane >> 2;        // 0..7
    const int lc = (lane & 3) * 2;   // 0,2,4,6
    const int warp_m = (wid & 1) * 32;
    const int warp_n = (wid >> 1) * 64;

    const int block_m = blockIdx.x * 64;
    const int c = block_m >> 14;           // view index
    const int b0 = block_m & (NB - 1);
    const float* Abase = X + (size_t)b0 * (NC * ND) + (size_t)c * ND;

    // A: 64 rows x 32 fp32; 4 passes; row = p*16 + (t>>3), k = (t&7)*4
    const int ar = t >> 3;       // 0..15
    const int ak = (t & 7) * 4;  // 0..28
    // B: 128 rows x 32 bf16; 4 passes; row = p*32 + (t>>2), k = (t&3)*8
    const int br = t >> 2;       // 0..31
    const int bk = (t & 3) * 8;  // 0,8,16,24

    float acc[2][8][4];
    #pragma unroll
    for (int mi = 0; mi < 2; mi++)
        #pragma unroll
        for (int ni = 0; ni < 8; ni++)
            #pragma unroll
            for (int j = 0; j < 4; j++) acc[mi][ni][j] = 0.0f;
    float rn[4] = {0, 0, 0, 0};

    float4 pav[4];
    uint4 pbh[4], pbl[4];

    // ---- prefetch chunk 0 ----
    #pragma unroll
    for (int p = 0; p < 4; p++)
        pav[p] = *(const float4*)(Abase + (size_t)(p * 16 + ar) * (NC * ND) + ak);
    #pragma unroll
    for (int p = 0; p < 4; p++) {
        pbh[p] = *(const uint4*)&g_cent_h[(p * 32 + br) * ND + bk];
        pbl[p] = *(const uint4*)&g_cent_l[(p * 32 + br) * ND + bk];
    }

    // ---- store chunk 0 into stage 0 ----
    #pragma unroll
    for (int p = 0; p < 4; p++) {
        float4 v = pav[p];
        rn[p] += v.x * v.x + v.y * v.y + v.z * v.z + v.w * v.w;
        uint32_t h0 = pack_bf16(v.x, v.y);
        uint32_t h1 = pack_bf16(v.z, v.w);
        uint32_t l0 = pack_bf16(v.x - bf_lo(h0), v.y - bf_hi(h0));
        uint32_t l1 = pack_bf16(v.z - bf_lo(h1), v.w - bf_hi(h1));
        int r = p * 16 + ar;
        *(uint2*)&sAh[r * LDSS + ak] = make_uint2(h0, h1);
        *(uint2*)&sAl[r * LDSS + ak] = make_uint2(l0, l1);
    }
    #pragma unroll
    for (int p = 0; p < 4; p++) {
        int g = p * 32 + br;
        *(uint4*)&sBh[g * LDSS + bk] = pbh[p];
        *(uint4*)&sBl[g * LDSS + bk] = pbl[p];
    }
    __syncthreads();

    for (int chk = 0; chk < NCHUNK; chk++) {
        const int cur = chk & 1;
        const int nxt = cur ^ 1;
        const bool has_next = (chk + 1 < NCHUNK);

        // ---- issue global loads for next chunk (overlap with MMA) ----
        if (has_next) {
            const int k0 = (chk + 1) * BK;
            #pragma unroll
            for (int p = 0; p < 4; p++)
                pav[p] = *(const float4*)(Abase + (size_t)(p * 16 + ar) * (NC * ND) + k0 + ak);
            #pragma unroll
            for (int p = 0; p < 4; p++) {
                pbh[p] = *(const uint4*)&g_cent_h[(p * 32 + br) * ND + k0 + bk];
                pbl[p] = *(const uint4*)&g_cent_l[(p * 32 + br) * ND + k0 + bk];
            }
        }

        // ---- MMA over current stage ----
        const __nv_bfloat16* cAh = sAh + cur * (64 * LDSS);
        const __nv_bfloat16* cAl = sAl + cur * (64 * LDSS);
        const __nv_bfloat16* cBh = sBh + cur * (128 * LDSS);
        const __nv_bfloat16* cBl = sBl + cur * (128 * LDSS);
        #pragma unroll
        for (int kk = 0; kk < BK; kk += 16) {
            uint32_t ah[2][4], al[2][4];
            #pragma unroll
            for (int mi = 0; mi < 2; mi++) {
                int m = warp_m + mi * 16;
                ah[mi][0] = *(const uint32_t*)&cAh[(m + lr) * LDSS + kk + lc];
                ah[mi][1] = *(const uint32_t*)&cAh[(m + lr + 8) * LDSS + kk + lc];
                ah[mi][2] = *(const uint32_t*)&cAh[(m + lr) * LDSS + kk + lc + 8];
                ah[mi][3] = *(const uint32_t*)&cAh[(m + lr + 8) * LDSS + kk + lc + 8];
                al[mi][0] = *(const uint32_t*)&cAl[(m + lr) * LDSS + kk + lc];
                al[mi][1] = *(const uint32_t*)&cAl[(m + lr + 8) * LDSS + kk + lc];
                al[mi][2] = *(const uint32_t*)&cAl[(m + lr) * LDSS + kk + lc + 8];
                al[mi][3] = *(const uint32_t*)&cAl[(m + lr + 8) * LDSS + kk + lc + 8];
            }
            uint32_t bh[8][2], bl[8][2];
            #pragma unroll
            for (int ni = 0; ni < 8; ni++) {
                int g = warp_n + ni * 8 + lr;
                bh[ni][0] = *(const uint32_t*)&cBh[g * LDSS + kk + lc];
                bh[ni][1] = *(const uint32_t*)&cBh[g * LDSS + kk + lc + 8];
                bl[ni][0] = *(const uint32_t*)&cBl[g * LDSS + kk + lc];
                bl[ni][1] = *(const uint32_t*)&cBl[g * LDSS + kk + lc + 8];
            }
            #pragma unroll
            for (int mi = 0; mi < 2; mi++)
                #pragma unroll
                for (int ni = 0; ni < 8; ni++) {
                    hmma_bf16(acc[mi][ni], ah[mi], bh[ni]);
                    hmma_bf16(acc[mi][ni], ah[mi], bl[ni]);
                    hmma_bf16(acc[mi][ni], al[mi], bh[ni]);
                }
        }

        // ---- convert & store next chunk into other stage ----
        if (has_next) {
            __nv_bfloat16* nAh = sAh + nxt * (64 * LDSS);
            __nv_bfloat16* nAl = sAl + nxt * (64 * LDSS);
            __nv_bfloat16* nBh = sBh + nxt * (128 * LDSS);
            __nv_bfloat16* nBl = sBl + nxt * (128 * LDSS);
            #pragma unroll
            for (int p = 0; p < 4; p++) {
                float4 v = pav[p];
                rn[p] += v.x * v.x + v.y * v.y + v.z * v.z + v.w * v.w;
                uint32_t h0 = pack_bf16(v.x, v.y);
                uint32_t h1 = pack_bf16(v.z, v.w);
                uint32_t l0 = pack_bf16(v.x - bf_lo(h0), v.y - bf_hi(h0));
                uint32_t l1 = pack_bf16(v.z - bf_lo(h1), v.w - bf_hi(h1));
                int r = p * 16 + ar;
                *(uint2*)&nAh[r * LDSS + ak] = make_uint2(h0, h1);
                *(uint2*)&nAl[r * LDSS + ak] = make_uint2(l0, l1);
            }
            #pragma unroll
            for (int p = 0; p < 4; p++) {
                int g = p * 32 + br;
                *(uint4*)&nBh[g * LDSS + bk] = pbh[p];
                *(uint4*)&nBl[g * LDSS + bk] = pbl[p];
            }
        }
        __syncthreads();
    }

    // ---- rownorm: reduce over 8 lanes sharing each row ----
    #pragma unroll
    for (int p = 0; p < 4; p++) {
        float v = rn[p];
        v += __shfl_xor_sync(0xFFFFFFFFu, v, 1);
        v += __shfl_xor_sync(0xFFFFFFFFu, v, 2);
        v += __shfl_xor_sync(0xFFFFFFFFu, v, 4);
        if ((t & 7) == 0) g_rownorm[block_m + p * 16 + ar] = v;
    }

    // ---- epilogue: write S ----
    #pragma unroll
    for (int mi = 0; mi < 2; mi++) {
        #pragma unroll
        for (int ni = 0; ni < 8; ni++) {
            int row = block_m + warp_m + mi * 16 + lr;
            int col = warp_n + ni * 8 + lc;
            *(float2*)&g_S[(size_t)row * KG + col] =
                make_float2(acc[mi][ni][0], acc[mi][ni][1]);
            *(float2*)&g_S[(size_t)(row + 8) * KG + col] =
                make_float2(acc[mi][ni][2], acc[mi][ni][3]);
        }
    }
}

// ---------------- K3: per-row dist -> per-group sum of sqrt(dist) ----------------
__global__ void dist_kernel() {
    __shared__ float bins[KG];
    int t = threadIdx.x;
    if (t < KG) bins[t] = 0.0f;
    __syncthreads();
    int i = blockIdx.x * 256 + t;
    int b = i & (NB - 1);
    int g = g_gid[b];
    float s = g_S[(size_t)i * KG + g];
    float d2 = g_rownorm[i] - 2.0f * s + g_cnorm[g];
    float dist = sqrtf(fmaxf(d2, 0.0f));
    atomicAdd(&bins[g], sqrtf(dist));
    __syncthreads();
    if (t < KG) atomicAdd(&g_sqsum[t], bins[t]);
}

// ---------------- K4: density ----------------
__global__ void density_kernel() {
    int t = threadIdx.x;  // 128
    __shared__ float dens[KG];
    __shared__ float red[KG];
    __shared__ float sorted[KG];

    float cnt = g_counts[t];
    float d = (g_sqsum[t] / cnt) / logf(cnt + 10.0f);
    bool invalid = (cnt <= 1.0f);
    red[t] = invalid ? -3.4e38f : d;
    __syncthreads();
    for (int off = 64; off; off >>= 1) {
        if (t < off) red[t] = fmaxf(red[t], red[t + off]);
        __syncthreads();
    }
    float dmax = red[0];
    __syncthreads();
    if (invalid) d = dmax;
    dens[t] = d;
    __syncthreads();

    int rank = 0;
    float v = d;
    for (int j = 0; j < KG; j++) {
        float w = dens[j];
        rank += (int)((w < v) || ((w == v) && (j < t)));
    }
    sorted[rank] = v;
    __syncthreads();

    float qlo = sorted[12] + 0.7f * (sorted[13] - sorted[12]);
    float qhi = sorted[114] + 0.3f * (sorted[115] - sorted[114]);
    float dc = fminf(fmaxf(d, qlo), qhi);
    red[t] = dc;
    __syncthreads();
    for (int off = 64; off; off >>= 1) {
        if (t < off) red[t] += red[t + off];
        __syncthreads();
    }
    float mean = red[0] * (1.0f / 128.0f);
    float fin = 0.1f * dc / mean;
    g_invdens[t] = 1.0f / fin;
}

// ---------------- K5: masked log-softmax loss ----------------
__global__ __launch_bounds__(256) void loss_kernel(const int* __restrict__ subject,
                                                   const int* __restrict__ labels,
                                                   float* __restrict__ out) {
    int warp_in_block = threadIdx.x >> 5;
    int lane = threadIdx.x & 31;
    int i = blockIdx.x * 8 + warp_in_block;
    int b = i & (NB - 1);

    float4 sv = *(const float4*)&g_S[(size_t)i * KG + lane * 4];
    float4 idv = *(const float4*)&g_invdens[lane * 4];
    float s0 = sv.x * idv.x, s1 = sv.y * idv.y, s2 = sv.z * idv.z, s3 = sv.w * idv.w;

    float mx = fmaxf(fmaxf(s0, s1), fmaxf(s2, s3));
    #pragma unroll
    for (int off = 16; off; off >>= 1) mx = fmaxf(mx, __shfl_xor_sync(0xFFFFFFFFu, mx, off));

    int sub = subject[b];
    int lab = labels[b];

    float sim[4] = {s0, s1, s2, s3};
    float sumexp = 0.0f, possum = 0.0f;
    #pragma unroll
    for (int j = 0; j < 4; j++) {
        int g = lane * 4 + j;
        bool m = ((g & 7) == lab) && ((g >> 3) != sub);
        float p = m ? (sim[j] - mx) : 0.0f;
        sumexp += expf(p);
        possum += p;
    }
    #pragma unroll
    for (int off = 16; off; off >>= 1) {
        sumexp += __shfl_xor_sync(0xFFFFFFFFu, sumexp, off);
        possum += __shfl_xor_sync(0xFFFFFFFFu, possum, off);
    }

    __shared__ float wloss[8];
    if (lane == 0)
        wloss[warp_in_block] = logf(sumexp) - possum * (1.0f / 15.0f);
    __syncthreads();
    if (threadIdx.x == 0) {
        float s = 0.0f;
        #pragma unroll
        for (int w = 0; w < 8; w++) s += wloss[w];
        atomicAdd(out, s * (1.0f / (float)NROWS));
    }
}

// ---------------- launch ----------------
extern "C" void kernel_launch(void* const* d_in, const int* in_sizes, int n_in,
                              void* d_out, int out_size) {
    const float* X       = (const float*)d_in[0];
    const int*   subject = (const int*)d_in[1];
    const int*   labels  = (const int*)d_in[2];
    float* out = (float*)d_out;

    static bool attr_set = false;
    if (!attr_set) {
        cudaFuncSetAttribute(gemm_kernel,
                             cudaFuncAttributeMaxDynamicSharedMemorySize, DYN_SMEM);
        attr_set = true;
    }

    zero_kernel<<<1, 128>>>(out);
    hist_kernel<<<NB / 256, 256>>>(subject, labels);
    offsets_kernel<<<1, 128>>>();
    scatter_kernel<<<64, 256>>>();
    dim3 cgrid(ND / 256, KG);
    centroid_kernel<<<cgrid, 256>>>(X);
    gemm_kernel<<<NROWS / 64, 128, DYN_SMEM>>>(X);
    dist_kernel<<<NROWS / 256, 256>>>();
    density_kernel<<<1, 128>>>();
    loss_kernel<<<NROWS / 8, 256>>>(subject, labels, out);
}